// round 11
// baseline (speedup 1.0000x reference)
#include <cuda_runtime.h>
#include <cuda_fp16.h>
#include <cstdint>

#define DIMM   4096
#define KVDIM  1024
#define SEQ    2048
#define NBATCH 2
#define NHEAD  32
#define HD     128
#define MROWS  (NBATCH * SEQ)           // 4096 token rows
#define QKVD   (DIMM + 2 * KVDIM)       // 6144 fused projection width

// ---------------------------------------------------------------------------
// Scratch (static device globals -- allocation-guard safe), all fp16
// ---------------------------------------------------------------------------
__device__ __half g_xh  [(size_t)MROWS * DIMM];    // x converted
__device__ __half g_qkv [(size_t)MROWS * QKVD];    // fused q|k|v output
__device__ __half g_oh  [(size_t)MROWS * DIMM];    // attention out
__device__ __half g_wt  [(size_t)QKVD * DIMM];     // [wq^T*s | wk^T | wv^T]  [N,K]
__device__ __half g_wot [(size_t)DIMM * DIMM];     // wo^T [N,K]

// ---------------------------------------------------------------------------
// Helpers
// ---------------------------------------------------------------------------
__device__ __forceinline__ uint32_t smem_u32(const void* p) {
    uint32_t a;
    asm("{ .reg .u64 t; cvta.to.shared.u64 t, %1; cvt.u32.u64 %0, t; }" : "=r"(a) : "l"(p));
    return a;
}

__device__ __forceinline__ void mma_f16(float* d, uint32_t a0, uint32_t a1,
                                        uint32_t a2, uint32_t a3,
                                        uint32_t b0, uint32_t b1) {
    asm volatile(
        "mma.sync.aligned.m16n8k16.row.col.f32.f16.f16.f32 "
        "{%0,%1,%2,%3},{%4,%5,%6,%7},{%8,%9},{%0,%1,%2,%3};"
        : "+f"(d[0]), "+f"(d[1]), "+f"(d[2]), "+f"(d[3])
        : "r"(a0), "r"(a1), "r"(a2), "r"(a3), "r"(b0), "r"(b1));
}

__device__ __forceinline__ void ldsm_x4(uint32_t& r0, uint32_t& r1,
                                        uint32_t& r2, uint32_t& r3, uint32_t addr) {
    asm volatile("ldmatrix.sync.aligned.m8n8.x4.shared.b16 {%0,%1,%2,%3}, [%4];"
                 : "=r"(r0), "=r"(r1), "=r"(r2), "=r"(r3) : "r"(addr));
}
__device__ __forceinline__ void ldsm_x4_t(uint32_t& r0, uint32_t& r1,
                                          uint32_t& r2, uint32_t& r3, uint32_t addr) {
    asm volatile("ldmatrix.sync.aligned.m8n8.x4.trans.shared.b16 {%0,%1,%2,%3}, [%4];"
                 : "=r"(r0), "=r"(r1), "=r"(r2), "=r"(r3) : "r"(addr));
}

__device__ __forceinline__ uint32_t pack_h2(float lo, float hi) {
    __half2 h = __floats2half2_rn(lo, hi);
    return *(uint32_t*)&h;
}

#define CP16(dst, src) \
    asm volatile("cp.async.cg.shared.global [%0], [%1], 16;" :: "r"(dst), "l"(src))
#define CP_COMMIT() asm volatile("cp.async.commit_group;")

// ---------------------------------------------------------------------------
// Pre-pass kernels
// ---------------------------------------------------------------------------
__global__ void conv_half_kernel(const float4* __restrict__ src,
                                 uint2* __restrict__ dst, int n4) {
    int i = blockIdx.x * blockDim.x + threadIdx.x;
    if (i < n4) {
        float4 v = src[i];
        uint2 u;
        u.x = pack_h2(v.x, v.y);
        u.y = pack_h2(v.z, v.w);
        dst[i] = u;
    }
}

// One launch: transpose+convert all 4 weights. z selects matrix.
__global__ void weights_prep_kernel(const float* __restrict__ wq,
                                    const float* __restrict__ wk,
                                    const float* __restrict__ wv,
                                    const float* __restrict__ wo,
                                    float qscale) {
    const int z = blockIdx.z;
    const float* src;
    __half* dst;
    int C;
    float mul = 1.f;
    if (z == 0)      { src = wq; dst = g_wt;                                 C = DIMM;  mul = qscale; }
    else if (z == 1) { src = wk; dst = g_wt + (size_t)DIMM * DIMM;           C = KVDIM; }
    else if (z == 2) { src = wv; dst = g_wt + (size_t)(DIMM + KVDIM) * DIMM; C = KVDIM; }
    else             { src = wo; dst = g_wot;                                C = DIMM;  }
    const int R = DIMM;
    if (blockIdx.x * 32 >= C) return;

    __shared__ float t[32][33];
    int bx = blockIdx.x * 32, by = blockIdx.y * 32;
    int x = bx + threadIdx.x;
#pragma unroll
    for (int i = threadIdx.y; i < 32; i += 8)
        t[i][threadIdx.x] = src[(size_t)(by + i) * C + x];
    __syncthreads();
    int ox = by + threadIdx.x;
#pragma unroll
    for (int i = threadIdx.y; i < 32; i += 8)
        dst[(size_t)(bx + i) * R + ox] = __float2half(t[threadIdx.x][i] * mul);
}

// ---------------------------------------------------------------------------
// fp16 GEMM (round-5 shape + software-pipelined fragments):
// C[M,N] = A[M,K] @ Bt[N,K]^T. CTA 128x128, k-tile 32, 4-stage cp.async,
// 8 warps (4m x 2n), warp 32x64. A-frags hoisted per k-tile; B-frags
// double-buffered so each ldsm issues under the previous frag's 8 mma.
// ---------------------------------------------------------------------------
#define GST   40                 // smem row stride (halves): 32 + 8 pad
#define ASTH  (128 * GST)        // halves per stage per operand
#define NST   4
#define GEMM_SMEM (NST * 2 * ASTH * 2)   // bytes = 81920

template <typename OutT>
__global__ void __launch_bounds__(256) gemm_f16_kernel(
    const __half* __restrict__ A, const __half* __restrict__ Bt,
    OutT* __restrict__ C, int M, int N, int K)
{
    extern __shared__ __half sm[];
    __half* As = sm;
    __half* Bs = sm + NST * ASTH;
    const uint32_t smA = smem_u32(As), smB = smem_u32(Bs);

    const int tid = threadIdx.x, warp = tid >> 5, lane = tid & 31;
    const int wm = warp >> 1, wn = warp & 1;
    const int g = lane >> 2, q = lane & 3;
    const long brow = (long)blockIdx.y * 128;
    const long bcol = (long)blockIdx.x * 128;

    float acc[2][8][4];
#pragma unroll
    for (int i = 0; i < 2; i++)
#pragma unroll
        for (int j = 0; j < 8; j++)
#pragma unroll
            for (int k = 0; k < 4; k++) acc[i][j][k] = 0.f;

    const int r_ld = tid >> 2, c_ld = tid & 3;
    const __half* gA0 = A + (brow + r_ld) * (long)K + c_ld * 8;
    const __half* gB0 = Bt + (bcol + r_ld) * (long)K + c_ld * 8;
    const uint32_t sA0 = smA + (r_ld * GST + c_ld * 8) * 2;
    const uint32_t sB0 = smB + (r_ld * GST + c_ld * 8) * 2;
    const long rowK64 = 64 * (long)K;

    const int NKT = K >> 5;

#define G_LOAD(s, kt) do {                                                   \
        uint32_t so = (uint32_t)(s) * (ASTH * 2);                            \
        long go = (long)(kt) * 32;                                           \
        CP16(sA0 + so,                 gA0 + go);                            \
        CP16(sA0 + so + 64 * GST * 2,  gA0 + go + rowK64);                   \
        CP16(sB0 + so,                 gB0 + go);                            \
        CP16(sB0 + so + 64 * GST * 2,  gB0 + go + rowK64);                   \
    } while (0)

    for (int s = 0; s < NST - 1; s++) { G_LOAD(s, s); CP_COMMIT(); }

    uint32_t aAddr[2], bAddr[4];
#pragma unroll
    for (int mt = 0; mt < 2; mt++)
        aAddr[mt] = smA + (((wm * 32 + mt * 16 + (lane & 15)) * GST) +
                           ((lane & 16) ? 8 : 0)) * 2;
#pragma unroll
    for (int np = 0; np < 4; np++)
        bAddr[np] = smB + (((wn * 64 + np * 16 + (lane & 7) + ((lane & 16) ? 8 : 0)) * GST) +
                           ((lane & 8) ? 8 : 0)) * 2;

    for (int kt = 0; kt < NKT; kt++) {
        const int s = kt & (NST - 1);
        asm volatile("cp.async.wait_group 2;");
        __syncthreads();
        const int nxt = kt + NST - 1;
        if (nxt < NKT) G_LOAD(nxt & (NST - 1), nxt);
        CP_COMMIT();

        const uint32_t so = (uint32_t)s * (ASTH * 2);

        // hoist all A fragments for both k-steps
        uint32_t af[2][2][4];
#pragma unroll
        for (int ks = 0; ks < 2; ks++)
#pragma unroll
            for (int mt = 0; mt < 2; mt++)
                ldsm_x4(af[ks][mt][0], af[ks][mt][1], af[ks][mt][2], af[ks][mt][3],
                        aAddr[mt] + so + ks * 32);

        // B fragments double-buffered: ldsm(next) issues before mma(cur)
        uint32_t bf[2][4];
        ldsm_x4(bf[0][0], bf[0][1], bf[0][2], bf[0][3], bAddr[0] + so);
#pragma unroll
        for (int ks = 0; ks < 2; ks++) {
#pragma unroll
            for (int np = 0; np < 4; np++) {
                const int cur = np & 1, nx = cur ^ 1;
                if (np < 3)
                    ldsm_x4(bf[nx][0], bf[nx][1], bf[nx][2], bf[nx][3],
                            bAddr[np + 1] + so + ks * 32);
                else if (ks == 0)
                    ldsm_x4(bf[nx][0], bf[nx][1], bf[nx][2], bf[nx][3],
                            bAddr[0] + so + 32);
                mma_f16(acc[0][2 * np],     af[ks][0][0], af[ks][0][1],
                        af[ks][0][2], af[ks][0][3], bf[cur][0], bf[cur][1]);
                mma_f16(acc[1][2 * np],     af[ks][1][0], af[ks][1][1],
                        af[ks][1][2], af[ks][1][3], bf[cur][0], bf[cur][1]);
                mma_f16(acc[0][2 * np + 1], af[ks][0][0], af[ks][0][1],
                        af[ks][0][2], af[ks][0][3], bf[cur][2], bf[cur][3]);
                mma_f16(acc[1][2 * np + 1], af[ks][1][0], af[ks][1][1],
                        af[ks][1][2], af[ks][1][3], bf[cur][2], bf[cur][3]);
            }
        }
    }

#pragma unroll
    for (int mt = 0; mt < 2; mt++) {
        long r0 = brow + wm * 32 + mt * 16 + g;
#pragma unroll
        for (int nt = 0; nt < 8; nt++) {
            long c = bcol + wn * 64 + nt * 8 + q * 2;
            if constexpr (sizeof(OutT) == 2) {
                *(uint32_t*)&C[r0 * N + c]       = pack_h2(acc[mt][nt][0], acc[mt][nt][1]);
                *(uint32_t*)&C[(r0 + 8) * N + c] = pack_h2(acc[mt][nt][2], acc[mt][nt][3]);
            } else {
                *(float2*)&C[r0 * N + c]       = make_float2(acc[mt][nt][0], acc[mt][nt][1]);
                *(float2*)&C[(r0 + 8) * N + c] = make_float2(acc[mt][nt][2], acc[mt][nt][3]);
            }
        }
    }
}

// ---------------------------------------------------------------------------
// Flash attention v3 (round-7 exact, best measured): 128 q-rows, 8 warps,
// 64-row KV tiles, software-pipelined QK(t+1)||softmax(t), base-2 softmax.
// ---------------------------------------------------------------------------
#define AST2    136
#define KVBUF   (64 * AST2 * 2)          // 17408 B per buffer
#define NKV     (SEQ / 64)               // 32 tiles
#define ATTN_SMEM (4 * KVBUF)            // 69632 B

__global__ void __launch_bounds__(256) attn_kernel()
{
    extern __shared__ __half sm[];
    const uint32_t smBase = smem_u32(sm);

    const int tid = threadIdx.x, warp = tid >> 5, lane = tid & 31;
    const int g = lane >> 2, q = lane & 3;
    const int qt = blockIdx.x, h = blockIdx.y, b = blockIdx.z;
    const int kvh = h >> 2;

    {
        const __half* qbase = g_qkv + ((size_t)b * SEQ + (size_t)qt * 128) * QKVD + h * HD;
#pragma unroll
        for (int i = 0; i < 8; i++) {
            int f = tid + i * 256;
            int r = f >> 4, c = f & 15;
            *(uint4*)&sm[r * AST2 + c * 8] = *(const uint4*)&qbase[(size_t)r * QKVD + c * 8];
        }
    }
    __syncthreads();

    uint32_t qa[8][4];
    {
        uint32_t qaddr = smBase + (((warp * 16 + (lane & 15)) * AST2) +
                                   ((lane & 16) ? 8 : 0)) * 2;
#pragma unroll
        for (int ks = 0; ks < 8; ks++)
            ldsm_x4(qa[ks][0], qa[ks][1], qa[ks][2], qa[ks][3], qaddr + ks * 32);
    }
    __syncthreads();

    const __half* kbase = g_qkv + (size_t)b * SEQ * QKVD + DIMM + kvh * HD;
    const __half* vbase = g_qkv + (size_t)b * SEQ * QKVD + DIMM + KVDIM + kvh * HD;

#define K_LOAD(kt, buf) do {                                                    \
        uint32_t kd = smBase + (uint32_t)(buf) * KVBUF;                         \
        size_t rowoff = (size_t)(kt) * 64;                                      \
        _Pragma("unroll")                                                       \
        for (int i = 0; i < 4; i++) {                                           \
            int f = tid + i * 256;                                              \
            int r = f >> 4, c = f & 15;                                         \
            CP16(kd + (r * AST2 + c * 8) * 2,                                   \
                 kbase + (rowoff + r) * QKVD + c * 8);                          \
        }                                                                       \
    } while (0)
#define V_LOAD(kt, buf) do {                                                    \
        uint32_t vd = smBase + 2 * KVBUF + (uint32_t)(buf) * KVBUF;             \
        size_t rowoff = (size_t)(kt) * 64;                                      \
        _Pragma("unroll")                                                       \
        for (int i = 0; i < 4; i++) {                                           \
            int f = tid + i * 256;                                              \
            int r = f >> 4, c = f & 15;                                         \
            CP16(vd + (r * AST2 + c * 8) * 2,                                   \
                 vbase + (rowoff + r) * QKVD + c * 8);                          \
        }                                                                       \
    } while (0)

    K_LOAD(0, 0); V_LOAD(0, 0); CP_COMMIT();
    K_LOAD(1, 1); CP_COMMIT();

    float oacc[16][4];
#pragma unroll
    for (int i = 0; i < 16; i++)
#pragma unroll
        for (int j = 0; j < 4; j++) oacc[i][j] = 0.f;
    float m0 = -1e30f, m1 = -1e30f, l0 = 0.f, l1 = 0.f;

    const uint32_t kBase = (((lane & 7) + ((lane & 16) ? 8 : 0)) * AST2 +
                            ((lane & 8) ? 8 : 0)) * 2;
    const uint32_t vBase = ((lane & 15) * AST2 + ((lane & 16) ? 8 : 0)) * 2;

    float sA[8][4], sB[8][4];

#define QK_TILE(buf, S) do {                                                     \
        uint32_t kb_ = smBase + (uint32_t)(buf) * KVBUF + kBase;                 \
        _Pragma("unroll")                                                        \
        for (int i_ = 0; i_ < 8; i_++)                                           \
            _Pragma("unroll")                                                    \
            for (int j_ = 0; j_ < 4; j_++) S[i_][j_] = 0.f;                      \
        _Pragma("unroll")                                                        \
        for (int ks_ = 0; ks_ < 8; ks_++) {                                      \
            _Pragma("unroll")                                                    \
            for (int np_ = 0; np_ < 4; np_++) {                                  \
                uint32_t b0_, b1_, b2_, b3_;                                     \
                ldsm_x4(b0_, b1_, b2_, b3_,                                      \
                        kb_ + np_ * (16 * AST2 * 2) + ks_ * 32);                 \
                mma_f16(S[2 * np_],     qa[ks_][0], qa[ks_][1], qa[ks_][2],      \
                        qa[ks_][3], b0_, b1_);                                   \
                mma_f16(S[2 * np_ + 1], qa[ks_][0], qa[ks_][1], qa[ks_][2],      \
                        qa[ks_][3], b2_, b3_);                                   \
            }                                                                    \
        }                                                                        \
    } while (0)

#define ATTN_BODY(kt, sc, sn) do {                                               \
        asm volatile("cp.async.wait_group 0;");                                  \
        __syncthreads();                                                         \
        if ((kt) + 2 < NKV) K_LOAD((kt) + 2, (kt) & 1);                          \
        if ((kt) + 1 < NKV) V_LOAD((kt) + 1, ((kt) + 1) & 1);                    \
        if ((kt) + 1 < NKV) CP_COMMIT();                                         \
        if ((kt) + 1 < NKV) QK_TILE(((kt) + 1) & 1, sn);                         \
        float tm0 = -1e30f, tm1 = -1e30f;                                        \
        _Pragma("unroll")                                                        \
        for (int nt = 0; nt < 8; nt++) {                                         \
            tm0 = fmaxf(tm0, fmaxf(sc[nt][0], sc[nt][1]));                       \
            tm1 = fmaxf(tm1, fmaxf(sc[nt][2], sc[nt][3]));                       \
        }                                                                        \
        tm0 = fmaxf(tm0, __shfl_xor_sync(0xffffffffu, tm0, 1));                  \
        tm0 = fmaxf(tm0, __shfl_xor_sync(0xffffffffu, tm0, 2));                  \
        tm1 = fmaxf(tm1, __shfl_xor_sync(0xffffffffu, tm1, 1));                  \
        tm1 = fmaxf(tm1, __shfl_xor_sync(0xffffffffu, tm1, 2));                  \
        float mn0 = fmaxf(m0, tm0), mn1 = fmaxf(m1, tm1);                        \
        float al0 = exp2f(m0 - mn0), al1 = exp2f(m1 - mn1);                      \
        m0 = mn0; m1 = mn1;                                                      \
        float rs0 = 0.f, rs1 = 0.f;                                              \
        _Pragma("unroll")                                                        \
        for (int nt = 0; nt < 8; nt++) {                                         \
            sc[nt][0] = exp2f(sc[nt][0] - mn0); rs0 += sc[nt][0];                \
            sc[nt][1] = exp2f(sc[nt][1] - mn0); rs0 += sc[nt][1];                \
            sc[nt][2] = exp2f(sc[nt][2] - mn1); rs1 += sc[nt][2];                \
            sc[nt][3] = exp2f(sc[nt][3] - mn1); rs1 += sc[nt][3];                \
        }                                                                        \
        rs0 += __shfl_xor_sync(0xffffffffu, rs0, 1);                             \
        rs0 += __shfl_xor_sync(0xffffffffu, rs0, 2);                             \
        rs1 += __shfl_xor_sync(0xffffffffu, rs1, 1);                             \
        rs1 += __shfl_xor_sync(0xffffffffu, rs1, 2);                             \
        l0 = l0 * al0 + rs0;                                                     \
        l1 = l1 * al1 + rs1;                                                     \
        _Pragma("unroll")                                                        \
        for (int nt = 0; nt < 16; nt++) {                                        \
            oacc[nt][0] *= al0; oacc[nt][1] *= al0;                              \
            oacc[nt][2] *= al1; oacc[nt][3] *= al1;                              \
        }                                                                        \
        uint32_t ph[4][4];                                                       \
        _Pragma("unroll")                                                        \
        for (int ks = 0; ks < 4; ks++) {                                         \
            ph[ks][0] = pack_h2(sc[2 * ks][0],     sc[2 * ks][1]);               \
            ph[ks][1] = pack_h2(sc[2 * ks][2],     sc[2 * ks][3]);               \
            ph[ks][2] = pack_h2(sc[2 * ks + 1][0], sc[2 * ks + 1][1]);           \
            ph[ks][3] = pack_h2(sc[2 * ks + 1][2], sc[2 * ks + 1][3]);           \
        }                                                                        \
        uint32_t vb_ = smBase + 2 * KVBUF + (uint32_t)((kt) & 1) * KVBUF + vBase;\
        _Pragma("unroll")                                                        \
        for (int ks = 0; ks < 4; ks++) {                                         \
            _Pragma("unroll")                                                    \
            for (int np = 0; np < 8; np++) {                                     \
                uint32_t b0_, b1_, b2_, b3_;                                     \
                ldsm_x4_t(b0_, b1_, b2_, b3_,                                    \
                          vb_ + np * 32 + ks * (16 * AST2 * 2));                 \
                mma_f16(oacc[2 * np],     ph[ks][0], ph[ks][1], ph[ks][2],       \
                        ph[ks][3], b0_, b1_);                                    \
                mma_f16(oacc[2 * np + 1], ph[ks][0], ph[ks][1], ph[ks][2],       \
                        ph[ks][3], b2_, b3_);                                    \
            }                                                                    \
        }                                                                        \
    } while (0)

    asm volatile("cp.async.wait_group 1;");
    __syncthreads();
    QK_TILE(0, sA);

    for (int kt = 0; kt < NKV; kt += 2) {
        ATTN_BODY(kt, sA, sB);
        ATTN_BODY(kt + 1, sB, sA);
    }

    float il0 = 1.f / l0, il1 = 1.f / l1;
    __half* ob = g_oh + ((size_t)b * SEQ + (size_t)qt * 128 + warp * 16) * DIMM + h * HD;
#pragma unroll
    for (int nt = 0; nt < 16; nt++) {
        int c = nt * 8 + q * 2;
        *(uint32_t*)&ob[(size_t)g * DIMM + c] =
            pack_h2(oacc[nt][0] * il0, oacc[nt][1] * il0);
        *(uint32_t*)&ob[(size_t)(g + 8) * DIMM + c] =
            pack_h2(oacc[nt][2] * il1, oacc[nt][3] * il1);
    }
}

// ---------------------------------------------------------------------------
extern "C" void kernel_launch(void* const* d_in, const int* in_sizes, int n_in,
                              void* d_out, int out_size)
{
    const float* x  = (const float*)d_in[0];
    const float* wq = (const float*)d_in[1];
    const float* wk = (const float*)d_in[2];
    const float* wv = (const float*)d_in[3];
    const float* wo = (const float*)d_in[4];
    float* out = (float*)d_out;

    __half *xh, *qkv, *oh, *wt, *wot;
    cudaGetSymbolAddress((void**)&xh,  g_xh);
    cudaGetSymbolAddress((void**)&qkv, g_qkv);
    cudaGetSymbolAddress((void**)&oh,  g_oh);
    cudaGetSymbolAddress((void**)&wt,  g_wt);
    cudaGetSymbolAddress((void**)&wot, g_wot);

    cudaFuncSetAttribute(gemm_f16_kernel<__half>,
                         cudaFuncAttributeMaxDynamicSharedMemorySize, GEMM_SMEM);
    cudaFuncSetAttribute(gemm_f16_kernel<float>,
                         cudaFuncAttributeMaxDynamicSharedMemorySize, GEMM_SMEM);
    cudaFuncSetAttribute(attn_kernel,
                         cudaFuncAttributeMaxDynamicSharedMemorySize, ATTN_SMEM);

    // scale = log2(e) / sqrt(HD): softmax computed in base-2 domain
    const float qscale = 1.44269504088896f * 0.08838834764831845f;

    // --- pre-pass (2 launches) ---
    weights_prep_kernel<<<dim3(DIMM / 32, DIMM / 32, 4), dim3(32, 8)>>>(
        wq, wk, wv, wo, qscale);
    {
        int n4 = MROWS * DIMM / 4;
        conv_half_kernel<<<(n4 + 255) / 256, 256>>>((const float4*)x, (uint2*)xh, n4);
    }

    // --- fused QKV projection: [MROWS, 6144] ---
    gemm_f16_kernel<__half><<<dim3(QKVD / 128, MROWS / 128), 256, GEMM_SMEM>>>(
        xh, wt, qkv, MROWS, QKVD, DIMM);

    // --- attention ---
    attn_kernel<<<dim3(SEQ / 128, NHEAD, NBATCH), 256, ATTN_SMEM>>>();

    // --- output projection (fp32 out) ---
    gemm_f16_kernel<float><<<dim3(DIMM / 128, MROWS / 128), 256, GEMM_SMEM>>>(
        oh, wot, out, MROWS, DIMM, DIMM);
}

// round 12
// speedup vs baseline: 1.1310x; 1.1310x over previous
#include <cuda_runtime.h>
#include <cuda_fp16.h>
#include <cstdint>

#define DIMM   4096
#define KVDIM  1024
#define SEQ    2048
#define NBATCH 2
#define NHEAD  32
#define HD     128
#define MROWS  (NBATCH * SEQ)           // 4096 token rows
#define QKVD   (DIMM + 2 * KVDIM)       // 6144 fused projection width

// ---------------------------------------------------------------------------
// Scratch (static device globals -- allocation-guard safe), all fp16
// ---------------------------------------------------------------------------
__device__ __half g_xh  [(size_t)MROWS * DIMM];    // x converted
__device__ __half g_qkv [(size_t)MROWS * QKVD];    // fused q|k|v output
__device__ __half g_oh  [(size_t)MROWS * DIMM];    // attention out
__device__ __half g_wt  [(size_t)QKVD * DIMM];     // [wq^T*s | wk^T | wv^T]  [N,K]
__device__ __half g_wot [(size_t)DIMM * DIMM];     // wo^T [N,K]

// ---------------------------------------------------------------------------
// Helpers
// ---------------------------------------------------------------------------
__device__ __forceinline__ uint32_t smem_u32(const void* p) {
    uint32_t a;
    asm("{ .reg .u64 t; cvta.to.shared.u64 t, %1; cvt.u32.u64 %0, t; }" : "=r"(a) : "l"(p));
    return a;
}

__device__ __forceinline__ void mma_f16(float* d, uint32_t a0, uint32_t a1,
                                        uint32_t a2, uint32_t a3,
                                        uint32_t b0, uint32_t b1) {
    asm volatile(
        "mma.sync.aligned.m16n8k16.row.col.f32.f16.f16.f32 "
        "{%0,%1,%2,%3},{%4,%5,%6,%7},{%8,%9},{%0,%1,%2,%3};"
        : "+f"(d[0]), "+f"(d[1]), "+f"(d[2]), "+f"(d[3])
        : "r"(a0), "r"(a1), "r"(a2), "r"(a3), "r"(b0), "r"(b1));
}

__device__ __forceinline__ void ldsm_x4(uint32_t& r0, uint32_t& r1,
                                        uint32_t& r2, uint32_t& r3, uint32_t addr) {
    asm volatile("ldmatrix.sync.aligned.m8n8.x4.shared.b16 {%0,%1,%2,%3}, [%4];"
                 : "=r"(r0), "=r"(r1), "=r"(r2), "=r"(r3) : "r"(addr));
}
__device__ __forceinline__ void ldsm_x4_t(uint32_t& r0, uint32_t& r1,
                                          uint32_t& r2, uint32_t& r3, uint32_t addr) {
    asm volatile("ldmatrix.sync.aligned.m8n8.x4.trans.shared.b16 {%0,%1,%2,%3}, [%4];"
                 : "=r"(r0), "=r"(r1), "=r"(r2), "=r"(r3) : "r"(addr));
}

__device__ __forceinline__ uint32_t pack_h2(float lo, float hi) {
    __half2 h = __floats2half2_rn(lo, hi);
    return *(uint32_t*)&h;
}

#define CP16(dst, src) \
    asm volatile("cp.async.cg.shared.global [%0], [%1], 16;" :: "r"(dst), "l"(src))
#define CP_COMMIT() asm volatile("cp.async.commit_group;")

// ---------------------------------------------------------------------------
// Fused pre-pass: one launch does all 4 weight transposes AND the x->half
// conversion. grid = (128, 128, 5), block = (32, 8).
//   z=0: wq (mul=qscale) -> g_wt            z=1: wk -> g_wt + DIMM*DIMM
//   z=2: wv -> g_wt + (DIMM+KVDIM)*DIMM     z=3: wo -> g_wot
//   z=4: convert x (16384 blocks x 256 threads = MROWS*DIMM/4 float4s)
// ---------------------------------------------------------------------------
__global__ void prep_kernel(const float* __restrict__ x,
                            const float* __restrict__ wq,
                            const float* __restrict__ wk,
                            const float* __restrict__ wv,
                            const float* __restrict__ wo,
                            float qscale) {
    const int z = blockIdx.z;

    if (z == 4) {
        // x conversion: 256 threads/block, 1 float4 each
        int t = threadIdx.y * 32 + threadIdx.x;
        int i = (blockIdx.y * gridDim.x + blockIdx.x) * 256 + t;
        float4 v = ((const float4*)x)[i];
        uint2 u;
        u.x = pack_h2(v.x, v.y);
        u.y = pack_h2(v.z, v.w);
        ((uint2*)g_xh)[i] = u;
        return;
    }

    const float* src;
    __half* dst;
    int C;
    float mul = 1.f;
    if (z == 0)      { src = wq; dst = g_wt;                                 C = DIMM;  mul = qscale; }
    else if (z == 1) { src = wk; dst = g_wt + (size_t)DIMM * DIMM;           C = KVDIM; }
    else if (z == 2) { src = wv; dst = g_wt + (size_t)(DIMM + KVDIM) * DIMM; C = KVDIM; }
    else             { src = wo; dst = g_wot;                                C = DIMM;  }
    const int R = DIMM;
    if (blockIdx.x * 32 >= C) return;

    __shared__ float t[32][33];
    int bx = blockIdx.x * 32, by = blockIdx.y * 32;
    int xc = bx + threadIdx.x;
#pragma unroll
    for (int i = threadIdx.y; i < 32; i += 8)
        t[i][threadIdx.x] = src[(size_t)(by + i) * C + xc];
    __syncthreads();
    int ox = by + threadIdx.x;
#pragma unroll
    for (int i = threadIdx.y; i < 32; i += 8)
        dst[(size_t)(bx + i) * R + ox] = __float2half(t[threadIdx.x][i] * mul);
}

// ---------------------------------------------------------------------------
// fp16 GEMM (FROZEN round-5 config, best measured):
// C[M,N] = A[M,K] @ Bt[N,K]^T. CTA 128x128, k-tile 32, 4-stage cp.async,
// 8 warps (4m x 2n), warp 32x64, launch_bounds(256,2).
// ---------------------------------------------------------------------------
#define GST   40                 // smem row stride (halves): 32 + 8 pad
#define ASTH  (128 * GST)        // halves per stage per operand
#define NST   4
#define GEMM_SMEM (NST * 2 * ASTH * 2)   // bytes = 81920

template <typename OutT>
__global__ void __launch_bounds__(256, 2) gemm_f16_kernel(
    const __half* __restrict__ A, const __half* __restrict__ Bt,
    OutT* __restrict__ C, int M, int N, int K)
{
    extern __shared__ __half sm[];
    __half* As = sm;
    __half* Bs = sm + NST * ASTH;
    const uint32_t smA = smem_u32(As), smB = smem_u32(Bs);

    const int tid = threadIdx.x, warp = tid >> 5, lane = tid & 31;
    const int wm = warp >> 1, wn = warp & 1;
    const int g = lane >> 2, q = lane & 3;
    const long brow = (long)blockIdx.y * 128;
    const long bcol = (long)blockIdx.x * 128;

    float acc[2][8][4];
#pragma unroll
    for (int i = 0; i < 2; i++)
#pragma unroll
        for (int j = 0; j < 8; j++)
#pragma unroll
            for (int k = 0; k < 4; k++) acc[i][j][k] = 0.f;

    const int r_ld = tid >> 2, c_ld = tid & 3;
    const __half* gA0 = A + (brow + r_ld) * (long)K + c_ld * 8;
    const __half* gB0 = Bt + (bcol + r_ld) * (long)K + c_ld * 8;
    const uint32_t sA0 = smA + (r_ld * GST + c_ld * 8) * 2;
    const uint32_t sB0 = smB + (r_ld * GST + c_ld * 8) * 2;
    const long rowK64 = 64 * (long)K;

    const int NKT = K >> 5;

#define G_LOAD(s, kt) do {                                                   \
        uint32_t so = (uint32_t)(s) * (ASTH * 2);                            \
        long go = (long)(kt) * 32;                                           \
        CP16(sA0 + so,                 gA0 + go);                            \
        CP16(sA0 + so + 64 * GST * 2,  gA0 + go + rowK64);                   \
        CP16(sB0 + so,                 gB0 + go);                            \
        CP16(sB0 + so + 64 * GST * 2,  gB0 + go + rowK64);                   \
    } while (0)

    for (int s = 0; s < NST - 1; s++) { G_LOAD(s, s); CP_COMMIT(); }

    uint32_t aAddr[2], bAddr[4];
#pragma unroll
    for (int mt = 0; mt < 2; mt++)
        aAddr[mt] = smA + (((wm * 32 + mt * 16 + (lane & 15)) * GST) +
                           ((lane & 16) ? 8 : 0)) * 2;
#pragma unroll
    for (int np = 0; np < 4; np++)
        bAddr[np] = smB + (((wn * 64 + np * 16 + (lane & 7) + ((lane & 16) ? 8 : 0)) * GST) +
                           ((lane & 8) ? 8 : 0)) * 2;

    for (int kt = 0; kt < NKT; kt++) {
        const int s = kt & (NST - 1);
        asm volatile("cp.async.wait_group 2;");
        __syncthreads();
        const int nxt = kt + NST - 1;
        if (nxt < NKT) G_LOAD(nxt & (NST - 1), nxt);
        CP_COMMIT();

        const uint32_t so = (uint32_t)s * (ASTH * 2);
#pragma unroll
        for (int ks = 0; ks < 2; ks++) {
            uint32_t af[2][4];
#pragma unroll
            for (int mt = 0; mt < 2; mt++)
                ldsm_x4(af[mt][0], af[mt][1], af[mt][2], af[mt][3],
                        aAddr[mt] + so + ks * 32);
#pragma unroll
            for (int np = 0; np < 4; np++) {
                uint32_t b0, b1, b2, b3;
                ldsm_x4(b0, b1, b2, b3, bAddr[np] + so + ks * 32);
                mma_f16(acc[0][2 * np],     af[0][0], af[0][1], af[0][2], af[0][3], b0, b1);
                mma_f16(acc[1][2 * np],     af[1][0], af[1][1], af[1][2], af[1][3], b0, b1);
                mma_f16(acc[0][2 * np + 1], af[0][0], af[0][1], af[0][2], af[0][3], b2, b3);
                mma_f16(acc[1][2 * np + 1], af[1][0], af[1][1], af[1][2], af[1][3], b2, b3);
            }
        }
    }

#pragma unroll
    for (int mt = 0; mt < 2; mt++) {
        long r0 = brow + wm * 32 + mt * 16 + g;
#pragma unroll
        for (int nt = 0; nt < 8; nt++) {
            long c = bcol + wn * 64 + nt * 8 + q * 2;
            if constexpr (sizeof(OutT) == 2) {
                *(uint32_t*)&C[r0 * N + c]       = pack_h2(acc[mt][nt][0], acc[mt][nt][1]);
                *(uint32_t*)&C[(r0 + 8) * N + c] = pack_h2(acc[mt][nt][2], acc[mt][nt][3]);
            } else {
                *(float2*)&C[r0 * N + c]       = make_float2(acc[mt][nt][0], acc[mt][nt][1]);
                *(float2*)&C[(r0 + 8) * N + c] = make_float2(acc[mt][nt][2], acc[mt][nt][3]);
            }
        }
    }
}

// ---------------------------------------------------------------------------
// Flash attention v3 (FROZEN round-7 exact, best measured): 128 q-rows,
// 8 warps, 64-row KV tiles, software-pipelined QK(t+1)||softmax(t),
// base-2 softmax.
// ---------------------------------------------------------------------------
#define AST2    136
#define KVBUF   (64 * AST2 * 2)          // 17408 B per buffer
#define NKV     (SEQ / 64)               // 32 tiles
#define ATTN_SMEM (4 * KVBUF)            // 69632 B

__global__ void __launch_bounds__(256) attn_kernel()
{
    extern __shared__ __half sm[];
    const uint32_t smBase = smem_u32(sm);

    const int tid = threadIdx.x, warp = tid >> 5, lane = tid & 31;
    const int g = lane >> 2, q = lane & 3;
    const int qt = blockIdx.x, h = blockIdx.y, b = blockIdx.z;
    const int kvh = h >> 2;

    {
        const __half* qbase = g_qkv + ((size_t)b * SEQ + (size_t)qt * 128) * QKVD + h * HD;
#pragma unroll
        for (int i = 0; i < 8; i++) {
            int f = tid + i * 256;
            int r = f >> 4, c = f & 15;
            *(uint4*)&sm[r * AST2 + c * 8] = *(const uint4*)&qbase[(size_t)r * QKVD + c * 8];
        }
    }
    __syncthreads();

    uint32_t qa[8][4];
    {
        uint32_t qaddr = smBase + (((warp * 16 + (lane & 15)) * AST2) +
                                   ((lane & 16) ? 8 : 0)) * 2;
#pragma unroll
        for (int ks = 0; ks < 8; ks++)
            ldsm_x4(qa[ks][0], qa[ks][1], qa[ks][2], qa[ks][3], qaddr + ks * 32);
    }
    __syncthreads();

    const __half* kbase = g_qkv + (size_t)b * SEQ * QKVD + DIMM + kvh * HD;
    const __half* vbase = g_qkv + (size_t)b * SEQ * QKVD + DIMM + KVDIM + kvh * HD;

#define K_LOAD(kt, buf) do {                                                    \
        uint32_t kd = smBase + (uint32_t)(buf) * KVBUF;                         \
        size_t rowoff = (size_t)(kt) * 64;                                      \
        _Pragma("unroll")                                                       \
        for (int i = 0; i < 4; i++) {                                           \
            int f = tid + i * 256;                                              \
            int r = f >> 4, c = f & 15;                                         \
            CP16(kd + (r * AST2 + c * 8) * 2,                                   \
                 kbase + (rowoff + r) * QKVD + c * 8);                          \
        }                                                                       \
    } while (0)
#define V_LOAD(kt, buf) do {                                                    \
        uint32_t vd = smBase + 2 * KVBUF + (uint32_t)(buf) * KVBUF;             \
        size_t rowoff = (size_t)(kt) * 64;                                      \
        _Pragma("unroll")                                                       \
        for (int i = 0; i < 4; i++) {                                           \
            int f = tid + i * 256;                                              \
            int r = f >> 4, c = f & 15;                                         \
            CP16(vd + (r * AST2 + c * 8) * 2,                                   \
                 vbase + (rowoff + r) * QKVD + c * 8);                          \
        }                                                                       \
    } while (0)

    K_LOAD(0, 0); V_LOAD(0, 0); CP_COMMIT();
    K_LOAD(1, 1); CP_COMMIT();

    float oacc[16][4];
#pragma unroll
    for (int i = 0; i < 16; i++)
#pragma unroll
        for (int j = 0; j < 4; j++) oacc[i][j] = 0.f;
    float m0 = -1e30f, m1 = -1e30f, l0 = 0.f, l1 = 0.f;

    const uint32_t kBase = (((lane & 7) + ((lane & 16) ? 8 : 0)) * AST2 +
                            ((lane & 8) ? 8 : 0)) * 2;
    const uint32_t vBase = ((lane & 15) * AST2 + ((lane & 16) ? 8 : 0)) * 2;

    float sA[8][4], sB[8][4];

#define QK_TILE(buf, S) do {                                                     \
        uint32_t kb_ = smBase + (uint32_t)(buf) * KVBUF + kBase;                 \
        _Pragma("unroll")                                                        \
        for (int i_ = 0; i_ < 8; i_++)                                           \
            _Pragma("unroll")                                                    \
            for (int j_ = 0; j_ < 4; j_++) S[i_][j_] = 0.f;                      \
        _Pragma("unroll")                                                        \
        for (int ks_ = 0; ks_ < 8; ks_++) {                                      \
            _Pragma("unroll")                                                    \
            for (int np_ = 0; np_ < 4; np_++) {                                  \
                uint32_t b0_, b1_, b2_, b3_;                                     \
                ldsm_x4(b0_, b1_, b2_, b3_,                                      \
                        kb_ + np_ * (16 * AST2 * 2) + ks_ * 32);                 \
                mma_f16(S[2 * np_],     qa[ks_][0], qa[ks_][1], qa[ks_][2],      \
                        qa[ks_][3], b0_, b1_);                                   \
                mma_f16(S[2 * np_ + 1], qa[ks_][0], qa[ks_][1], qa[ks_][2],      \
                        qa[ks_][3], b2_, b3_);                                   \
            }                                                                    \
        }                                                                        \
    } while (0)

#define ATTN_BODY(kt, sc, sn) do {                                               \
        asm volatile("cp.async.wait_group 0;");                                  \
        __syncthreads();                                                         \
        if ((kt) + 2 < NKV) K_LOAD((kt) + 2, (kt) & 1);                          \
        if ((kt) + 1 < NKV) V_LOAD((kt) + 1, ((kt) + 1) & 1);                    \
        if ((kt) + 1 < NKV) CP_COMMIT();                                         \
        if ((kt) + 1 < NKV) QK_TILE(((kt) + 1) & 1, sn);                         \
        float tm0 = -1e30f, tm1 = -1e30f;                                        \
        _Pragma("unroll")                                                        \
        for (int nt = 0; nt < 8; nt++) {                                         \
            tm0 = fmaxf(tm0, fmaxf(sc[nt][0], sc[nt][1]));                       \
            tm1 = fmaxf(tm1, fmaxf(sc[nt][2], sc[nt][3]));                       \
        }                                                                        \
        tm0 = fmaxf(tm0, __shfl_xor_sync(0xffffffffu, tm0, 1));                  \
        tm0 = fmaxf(tm0, __shfl_xor_sync(0xffffffffu, tm0, 2));                  \
        tm1 = fmaxf(tm1, __shfl_xor_sync(0xffffffffu, tm1, 1));                  \
        tm1 = fmaxf(tm1, __shfl_xor_sync(0xffffffffu, tm1, 2));                  \
        float mn0 = fmaxf(m0, tm0), mn1 = fmaxf(m1, tm1);                        \
        float al0 = exp2f(m0 - mn0), al1 = exp2f(m1 - mn1);                      \
        m0 = mn0; m1 = mn1;                                                      \
        float rs0 = 0.f, rs1 = 0.f;                                              \
        _Pragma("unroll")                                                        \
        for (int nt = 0; nt < 8; nt++) {                                         \
            sc[nt][0] = exp2f(sc[nt][0] - mn0); rs0 += sc[nt][0];                \
            sc[nt][1] = exp2f(sc[nt][1] - mn0); rs0 += sc[nt][1];                \
            sc[nt][2] = exp2f(sc[nt][2] - mn1); rs1 += sc[nt][2];                \
            sc[nt][3] = exp2f(sc[nt][3] - mn1); rs1 += sc[nt][3];                \
        }                                                                        \
        rs0 += __shfl_xor_sync(0xffffffffu, rs0, 1);                             \
        rs0 += __shfl_xor_sync(0xffffffffu, rs0, 2);                             \
        rs1 += __shfl_xor_sync(0xffffffffu, rs1, 1);                             \
        rs1 += __shfl_xor_sync(0xffffffffu, rs1, 2);                             \
        l0 = l0 * al0 + rs0;                                                     \
        l1 = l1 * al1 + rs1;                                                     \
        _Pragma("unroll")                                                        \
        for (int nt = 0; nt < 16; nt++) {                                        \
            oacc[nt][0] *= al0; oacc[nt][1] *= al0;                              \
            oacc[nt][2] *= al1; oacc[nt][3] *= al1;                              \
        }                                                                        \
        uint32_t ph[4][4];                                                       \
        _Pragma("unroll")                                                        \
        for (int ks = 0; ks < 4; ks++) {                                         \
            ph[ks][0] = pack_h2(sc[2 * ks][0],     sc[2 * ks][1]);               \
            ph[ks][1] = pack_h2(sc[2 * ks][2],     sc[2 * ks][3]);               \
            ph[ks][2] = pack_h2(sc[2 * ks + 1][0], sc[2 * ks + 1][1]);           \
            ph[ks][3] = pack_h2(sc[2 * ks + 1][2], sc[2 * ks + 1][3]);           \
        }                                                                        \
        uint32_t vb_ = smBase + 2 * KVBUF + (uint32_t)((kt) & 1) * KVBUF + vBase;\
        _Pragma("unroll")                                                        \
        for (int ks = 0; ks < 4; ks++) {                                         \
            _Pragma("unroll")                                                    \
            for (int np = 0; np < 8; np++) {                                     \
                uint32_t b0_, b1_, b2_, b3_;                                     \
                ldsm_x4_t(b0_, b1_, b2_, b3_,                                    \
                          vb_ + np * 32 + ks * (16 * AST2 * 2));                 \
                mma_f16(oacc[2 * np],     ph[ks][0], ph[ks][1], ph[ks][2],       \
                        ph[ks][3], b0_, b1_);                                    \
                mma_f16(oacc[2 * np + 1], ph[ks][0], ph[ks][1], ph[ks][2],       \
                        ph[ks][3], b2_, b3_);                                    \
            }                                                                    \
        }                                                                        \
    } while (0)

    asm volatile("cp.async.wait_group 1;");
    __syncthreads();
    QK_TILE(0, sA);

    for (int kt = 0; kt < NKV; kt += 2) {
        ATTN_BODY(kt, sA, sB);
        ATTN_BODY(kt + 1, sB, sA);
    }

    float il0 = 1.f / l0, il1 = 1.f / l1;
    __half* ob = g_oh + ((size_t)b * SEQ + (size_t)qt * 128 + warp * 16) * DIMM + h * HD;
#pragma unroll
    for (int nt = 0; nt < 16; nt++) {
        int c = nt * 8 + q * 2;
        *(uint32_t*)&ob[(size_t)g * DIMM + c] =
            pack_h2(oacc[nt][0] * il0, oacc[nt][1] * il0);
        *(uint32_t*)&ob[(size_t)(g + 8) * DIMM + c] =
            pack_h2(oacc[nt][2] * il1, oacc[nt][3] * il1);
    }
}

// ---------------------------------------------------------------------------
extern "C" void kernel_launch(void* const* d_in, const int* in_sizes, int n_in,
                              void* d_out, int out_size)
{
    const float* x  = (const float*)d_in[0];
    const float* wq = (const float*)d_in[1];
    const float* wk = (const float*)d_in[2];
    const float* wv = (const float*)d_in[3];
    const float* wo = (const float*)d_in[4];
    float* out = (float*)d_out;

    __half *xh, *qkv, *oh, *wt, *wot;
    cudaGetSymbolAddress((void**)&xh,  g_xh);
    cudaGetSymbolAddress((void**)&qkv, g_qkv);
    cudaGetSymbolAddress((void**)&oh,  g_oh);
    cudaGetSymbolAddress((void**)&wt,  g_wt);
    cudaGetSymbolAddress((void**)&wot, g_wot);

    cudaFuncSetAttribute(gemm_f16_kernel<__half>,
                         cudaFuncAttributeMaxDynamicSharedMemorySize, GEMM_SMEM);
    cudaFuncSetAttribute(gemm_f16_kernel<float>,
                         cudaFuncAttributeMaxDynamicSharedMemorySize, GEMM_SMEM);
    cudaFuncSetAttribute(attn_kernel,
                         cudaFuncAttributeMaxDynamicSharedMemorySize, ATTN_SMEM);

    // scale = log2(e) / sqrt(HD): softmax computed in base-2 domain
    const float qscale = 1.44269504088896f * 0.08838834764831845f;

    // --- fused pre-pass (1 launch: 4 weight transposes + x conversion) ---
    prep_kernel<<<dim3(DIMM / 32, DIMM / 32, 5), dim3(32, 8)>>>(
        x, wq, wk, wv, wo, qscale);

    // --- fused QKV projection: [MROWS, 6144] ---
    gemm_f16_kernel<__half><<<dim3(QKVD / 128, MROWS / 128), 256, GEMM_SMEM>>>(
        xh, wt, qkv, MROWS, QKVD, DIMM);

    // --- attention ---
    attn_kernel<<<dim3(SEQ / 128, NHEAD, NBATCH), 256, ATTN_SMEM>>>();

    // --- output projection (fp32 out) ---
    gemm_f16_kernel<float><<<dim3(DIMM / 128, MROWS / 128), 256, GEMM_SMEM>>>(
        oh, wot, out, MROWS, DIMM, DIMM);
}

// round 13
// speedup vs baseline: 1.1323x; 1.0012x over previous
#include <cuda_runtime.h>
#include <cuda_fp16.h>
#include <cstdint>

#define DIMM   4096
#define KVDIM  1024
#define SEQ    2048
#define NBATCH 2
#define NHEAD  32
#define HD     128
#define MROWS  (NBATCH * SEQ)           // 4096 token rows
#define QKVD   (DIMM + 2 * KVDIM)       // 6144 fused projection width

// ---------------------------------------------------------------------------
// Scratch (static device globals -- allocation-guard safe), all fp16
// ---------------------------------------------------------------------------
__device__ __half g_xh  [(size_t)MROWS * DIMM];    // x converted
__device__ __half g_qkv [(size_t)MROWS * QKVD];    // fused q|k|v output
__device__ __half g_oh  [(size_t)MROWS * DIMM];    // attention out
__device__ __half g_wt  [(size_t)QKVD * DIMM];     // [wq^T*s | wk^T | wv^T]  [N,K]
__device__ __half g_wot [(size_t)DIMM * DIMM];     // wo^T [N,K]

// ---------------------------------------------------------------------------
// Helpers
// ---------------------------------------------------------------------------
__device__ __forceinline__ uint32_t smem_u32(const void* p) {
    uint32_t a;
    asm("{ .reg .u64 t; cvta.to.shared.u64 t, %1; cvt.u32.u64 %0, t; }" : "=r"(a) : "l"(p));
    return a;
}

__device__ __forceinline__ void mma_f16(float* d, uint32_t a0, uint32_t a1,
                                        uint32_t a2, uint32_t a3,
                                        uint32_t b0, uint32_t b1) {
    asm volatile(
        "mma.sync.aligned.m16n8k16.row.col.f32.f16.f16.f32 "
        "{%0,%1,%2,%3},{%4,%5,%6,%7},{%8,%9},{%0,%1,%2,%3};"
        : "+f"(d[0]), "+f"(d[1]), "+f"(d[2]), "+f"(d[3])
        : "r"(a0), "r"(a1), "r"(a2), "r"(a3), "r"(b0), "r"(b1));
}

__device__ __forceinline__ void ldsm_x4(uint32_t& r0, uint32_t& r1,
                                        uint32_t& r2, uint32_t& r3, uint32_t addr) {
    asm volatile("ldmatrix.sync.aligned.m8n8.x4.shared.b16 {%0,%1,%2,%3}, [%4];"
                 : "=r"(r0), "=r"(r1), "=r"(r2), "=r"(r3) : "r"(addr));
}
__device__ __forceinline__ void ldsm_x4_t(uint32_t& r0, uint32_t& r1,
                                          uint32_t& r2, uint32_t& r3, uint32_t addr) {
    asm volatile("ldmatrix.sync.aligned.m8n8.x4.trans.shared.b16 {%0,%1,%2,%3}, [%4];"
                 : "=r"(r0), "=r"(r1), "=r"(r2), "=r"(r3) : "r"(addr));
}

__device__ __forceinline__ uint32_t pack_h2(float lo, float hi) {
    __half2 h = __floats2half2_rn(lo, hi);
    return *(uint32_t*)&h;
}

#define CP16(dst, src) \
    asm volatile("cp.async.cg.shared.global [%0], [%1], 16;" :: "r"(dst), "l"(src))
#define CP_COMMIT() asm volatile("cp.async.commit_group;")

// ---------------------------------------------------------------------------
// Fused pre-pass: one launch does all 4 weight transposes AND the x->half
// conversion. grid = (128, 128, 5), block = (32, 8).
// ---------------------------------------------------------------------------
__global__ void prep_kernel(const float* __restrict__ x,
                            const float* __restrict__ wq,
                            const float* __restrict__ wk,
                            const float* __restrict__ wv,
                            const float* __restrict__ wo,
                            float qscale) {
    const int z = blockIdx.z;

    if (z == 4) {
        int t = threadIdx.y * 32 + threadIdx.x;
        int i = (blockIdx.y * gridDim.x + blockIdx.x) * 256 + t;
        float4 v = ((const float4*)x)[i];
        uint2 u;
        u.x = pack_h2(v.x, v.y);
        u.y = pack_h2(v.z, v.w);
        ((uint2*)g_xh)[i] = u;
        return;
    }

    const float* src;
    __half* dst;
    int C;
    float mul = 1.f;
    if (z == 0)      { src = wq; dst = g_wt;                                 C = DIMM;  mul = qscale; }
    else if (z == 1) { src = wk; dst = g_wt + (size_t)DIMM * DIMM;           C = KVDIM; }
    else if (z == 2) { src = wv; dst = g_wt + (size_t)(DIMM + KVDIM) * DIMM; C = KVDIM; }
    else             { src = wo; dst = g_wot;                                C = DIMM;  }
    const int R = DIMM;
    if (blockIdx.x * 32 >= C) return;

    __shared__ float t[32][33];
    int bx = blockIdx.x * 32, by = blockIdx.y * 32;
    int xc = bx + threadIdx.x;
#pragma unroll
    for (int i = threadIdx.y; i < 32; i += 8)
        t[i][threadIdx.x] = src[(size_t)(by + i) * C + xc];
    __syncthreads();
    int ox = by + threadIdx.x;
#pragma unroll
    for (int i = threadIdx.y; i < 32; i += 8)
        dst[(size_t)(bx + i) * R + ox] = __float2half(t[threadIdx.x][i] * mul);
}

// ---------------------------------------------------------------------------
// fp16 GEMM (round-5 shape, NST 4->5 for deeper L2-latency cover):
// C[M,N] = A[M,K] @ Bt[N,K]^T. CTA 128x128, k-tile 32, 5-stage cp.async,
// 8 warps (4m x 2n), warp 32x64, launch_bounds(256,2). 2x100KB smem fits.
// ---------------------------------------------------------------------------
#define GST   40                 // smem row stride (halves): 32 + 8 pad
#define ASTH  (128 * GST)        // halves per stage per operand
#define NST   5
#define GEMM_SMEM (NST * 2 * ASTH * 2)   // bytes = 102400

template <typename OutT>
__global__ void __launch_bounds__(256, 2) gemm_f16_kernel(
    const __half* __restrict__ A, const __half* __restrict__ Bt,
    OutT* __restrict__ C, int M, int N, int K)
{
    extern __shared__ __half sm[];
    __half* As = sm;
    __half* Bs = sm + NST * ASTH;
    const uint32_t smA = smem_u32(As), smB = smem_u32(Bs);

    const int tid = threadIdx.x, warp = tid >> 5, lane = tid & 31;
    const int wm = warp >> 1, wn = warp & 1;
    const int g = lane >> 2, q = lane & 3;
    const long brow = (long)blockIdx.y * 128;
    const long bcol = (long)blockIdx.x * 128;

    float acc[2][8][4];
#pragma unroll
    for (int i = 0; i < 2; i++)
#pragma unroll
        for (int j = 0; j < 8; j++)
#pragma unroll
            for (int k = 0; k < 4; k++) acc[i][j][k] = 0.f;

    const int r_ld = tid >> 2, c_ld = tid & 3;
    const __half* gA0 = A + (brow + r_ld) * (long)K + c_ld * 8;
    const __half* gB0 = Bt + (bcol + r_ld) * (long)K + c_ld * 8;
    const uint32_t sA0 = smA + (r_ld * GST + c_ld * 8) * 2;
    const uint32_t sB0 = smB + (r_ld * GST + c_ld * 8) * 2;
    const long rowK64 = 64 * (long)K;

    const int NKT = K >> 5;

#define G_LOAD(s, kt) do {                                                   \
        uint32_t so = (uint32_t)(s) * (ASTH * 2);                            \
        long go = (long)(kt) * 32;                                           \
        CP16(sA0 + so,                 gA0 + go);                            \
        CP16(sA0 + so + 64 * GST * 2,  gA0 + go + rowK64);                   \
        CP16(sB0 + so,                 gB0 + go);                            \
        CP16(sB0 + so + 64 * GST * 2,  gB0 + go + rowK64);                   \
    } while (0)

    for (int s = 0; s < NST - 1; s++) { G_LOAD(s, s); CP_COMMIT(); }

    uint32_t aAddr[2], bAddr[4];
#pragma unroll
    for (int mt = 0; mt < 2; mt++)
        aAddr[mt] = smA + (((wm * 32 + mt * 16 + (lane & 15)) * GST) +
                           ((lane & 16) ? 8 : 0)) * 2;
#pragma unroll
    for (int np = 0; np < 4; np++)
        bAddr[np] = smB + (((wn * 64 + np * 16 + (lane & 7) + ((lane & 16) ? 8 : 0)) * GST) +
                           ((lane & 8) ? 8 : 0)) * 2;

    int s = 0;
    for (int kt = 0; kt < NKT; kt++) {
        asm volatile("cp.async.wait_group 3;");
        __syncthreads();
        const int nxt = kt + NST - 1;
        if (nxt < NKT) {
            int ns = s + NST - 1; if (ns >= NST) ns -= NST;
            G_LOAD(ns, nxt);
        }
        CP_COMMIT();

        const uint32_t so = (uint32_t)s * (ASTH * 2);
#pragma unroll
        for (int ks = 0; ks < 2; ks++) {
            uint32_t af[2][4];
#pragma unroll
            for (int mt = 0; mt < 2; mt++)
                ldsm_x4(af[mt][0], af[mt][1], af[mt][2], af[mt][3],
                        aAddr[mt] + so + ks * 32);
#pragma unroll
            for (int np = 0; np < 4; np++) {
                uint32_t b0, b1, b2, b3;
                ldsm_x4(b0, b1, b2, b3, bAddr[np] + so + ks * 32);
                mma_f16(acc[0][2 * np],     af[0][0], af[0][1], af[0][2], af[0][3], b0, b1);
                mma_f16(acc[1][2 * np],     af[1][0], af[1][1], af[1][2], af[1][3], b0, b1);
                mma_f16(acc[0][2 * np + 1], af[0][0], af[0][1], af[0][2], af[0][3], b2, b3);
                mma_f16(acc[1][2 * np + 1], af[1][0], af[1][1], af[1][2], af[1][3], b2, b3);
            }
        }
        if (++s == NST) s = 0;
    }

#pragma unroll
    for (int mt = 0; mt < 2; mt++) {
        long r0 = brow + wm * 32 + mt * 16 + g;
#pragma unroll
        for (int nt = 0; nt < 8; nt++) {
            long c = bcol + wn * 64 + nt * 8 + q * 2;
            if constexpr (sizeof(OutT) == 2) {
                *(uint32_t*)&C[r0 * N + c]       = pack_h2(acc[mt][nt][0], acc[mt][nt][1]);
                *(uint32_t*)&C[(r0 + 8) * N + c] = pack_h2(acc[mt][nt][2], acc[mt][nt][3]);
            } else {
                *(float2*)&C[r0 * N + c]       = make_float2(acc[mt][nt][0], acc[mt][nt][1]);
                *(float2*)&C[(r0 + 8) * N + c] = make_float2(acc[mt][nt][2], acc[mt][nt][3]);
            }
        }
    }
}

// ---------------------------------------------------------------------------
// Flash attention v3 (FROZEN round-7 exact, best measured): 128 q-rows,
// 8 warps, 64-row KV tiles, software-pipelined QK(t+1)||softmax(t),
// base-2 softmax.
// ---------------------------------------------------------------------------
#define AST2    136
#define KVBUF   (64 * AST2 * 2)          // 17408 B per buffer
#define NKV     (SEQ / 64)               // 32 tiles
#define ATTN_SMEM (4 * KVBUF)            // 69632 B

__global__ void __launch_bounds__(256) attn_kernel()
{
    extern __shared__ __half sm[];
    const uint32_t smBase = smem_u32(sm);

    const int tid = threadIdx.x, warp = tid >> 5, lane = tid & 31;
    const int g = lane >> 2, q = lane & 3;
    const int qt = blockIdx.x, h = blockIdx.y, b = blockIdx.z;
    const int kvh = h >> 2;

    {
        const __half* qbase = g_qkv + ((size_t)b * SEQ + (size_t)qt * 128) * QKVD + h * HD;
#pragma unroll
        for (int i = 0; i < 8; i++) {
            int f = tid + i * 256;
            int r = f >> 4, c = f & 15;
            *(uint4*)&sm[r * AST2 + c * 8] = *(const uint4*)&qbase[(size_t)r * QKVD + c * 8];
        }
    }
    __syncthreads();

    uint32_t qa[8][4];
    {
        uint32_t qaddr = smBase + (((warp * 16 + (lane & 15)) * AST2) +
                                   ((lane & 16) ? 8 : 0)) * 2;
#pragma unroll
        for (int ks = 0; ks < 8; ks++)
            ldsm_x4(qa[ks][0], qa[ks][1], qa[ks][2], qa[ks][3], qaddr + ks * 32);
    }
    __syncthreads();

    const __half* kbase = g_qkv + (size_t)b * SEQ * QKVD + DIMM + kvh * HD;
    const __half* vbase = g_qkv + (size_t)b * SEQ * QKVD + DIMM + KVDIM + kvh * HD;

#define K_LOAD(kt, buf) do {                                                    \
        uint32_t kd = smBase + (uint32_t)(buf) * KVBUF;                         \
        size_t rowoff = (size_t)(kt) * 64;                                      \
        _Pragma("unroll")                                                       \
        for (int i = 0; i < 4; i++) {                                           \
            int f = tid + i * 256;                                              \
            int r = f >> 4, c = f & 15;                                         \
            CP16(kd + (r * AST2 + c * 8) * 2,                                   \
                 kbase + (rowoff + r) * QKVD + c * 8);                          \
        }                                                                       \
    } while (0)
#define V_LOAD(kt, buf) do {                                                    \
        uint32_t vd = smBase + 2 * KVBUF + (uint32_t)(buf) * KVBUF;             \
        size_t rowoff = (size_t)(kt) * 64;                                      \
        _Pragma("unroll")                                                       \
        for (int i = 0; i < 4; i++) {                                           \
            int f = tid + i * 256;                                              \
            int r = f >> 4, c = f & 15;                                         \
            CP16(vd + (r * AST2 + c * 8) * 2,                                   \
                 vbase + (rowoff + r) * QKVD + c * 8);                          \
        }                                                                       \
    } while (0)

    K_LOAD(0, 0); V_LOAD(0, 0); CP_COMMIT();
    K_LOAD(1, 1); CP_COMMIT();

    float oacc[16][4];
#pragma unroll
    for (int i = 0; i < 16; i++)
#pragma unroll
        for (int j = 0; j < 4; j++) oacc[i][j] = 0.f;
    float m0 = -1e30f, m1 = -1e30f, l0 = 0.f, l1 = 0.f;

    const uint32_t kBase = (((lane & 7) + ((lane & 16) ? 8 : 0)) * AST2 +
                            ((lane & 8) ? 8 : 0)) * 2;
    const uint32_t vBase = ((lane & 15) * AST2 + ((lane & 16) ? 8 : 0)) * 2;

    float sA[8][4], sB[8][4];

#define QK_TILE(buf, S) do {                                                     \
        uint32_t kb_ = smBase + (uint32_t)(buf) * KVBUF + kBase;                 \
        _Pragma("unroll")                                                        \
        for (int i_ = 0; i_ < 8; i_++)                                           \
            _Pragma("unroll")                                                    \
            for (int j_ = 0; j_ < 4; j_++) S[i_][j_] = 0.f;                      \
        _Pragma("unroll")                                                        \
        for (int ks_ = 0; ks_ < 8; ks_++) {                                      \
            _Pragma("unroll")                                                    \
            for (int np_ = 0; np_ < 4; np_++) {                                  \
                uint32_t b0_, b1_, b2_, b3_;                                     \
                ldsm_x4(b0_, b1_, b2_, b3_,                                      \
                        kb_ + np_ * (16 * AST2 * 2) + ks_ * 32);                 \
                mma_f16(S[2 * np_],     qa[ks_][0], qa[ks_][1], qa[ks_][2],      \
                        qa[ks_][3], b0_, b1_);                                   \
                mma_f16(S[2 * np_ + 1], qa[ks_][0], qa[ks_][1], qa[ks_][2],      \
                        qa[ks_][3], b2_, b3_);                                   \
            }                                                                    \
        }                                                                        \
    } while (0)

#define ATTN_BODY(kt, sc, sn) do {                                               \
        asm volatile("cp.async.wait_group 0;");                                  \
        __syncthreads();                                                         \
        if ((kt) + 2 < NKV) K_LOAD((kt) + 2, (kt) & 1);                          \
        if ((kt) + 1 < NKV) V_LOAD((kt) + 1, ((kt) + 1) & 1);                    \
        if ((kt) + 1 < NKV) CP_COMMIT();                                         \
        if ((kt) + 1 < NKV) QK_TILE(((kt) + 1) & 1, sn);                         \
        float tm0 = -1e30f, tm1 = -1e30f;                                        \
        _Pragma("unroll")                                                        \
        for (int nt = 0; nt < 8; nt++) {                                         \
            tm0 = fmaxf(tm0, fmaxf(sc[nt][0], sc[nt][1]));                       \
            tm1 = fmaxf(tm1, fmaxf(sc[nt][2], sc[nt][3]));                       \
        }                                                                        \
        tm0 = fmaxf(tm0, __shfl_xor_sync(0xffffffffu, tm0, 1));                  \
        tm0 = fmaxf(tm0, __shfl_xor_sync(0xffffffffu, tm0, 2));                  \
        tm1 = fmaxf(tm1, __shfl_xor_sync(0xffffffffu, tm1, 1));                  \
        tm1 = fmaxf(tm1, __shfl_xor_sync(0xffffffffu, tm1, 2));                  \
        float mn0 = fmaxf(m0, tm0), mn1 = fmaxf(m1, tm1);                        \
        float al0 = exp2f(m0 - mn0), al1 = exp2f(m1 - mn1);                      \
        m0 = mn0; m1 = mn1;                                                      \
        float rs0 = 0.f, rs1 = 0.f;                                              \
        _Pragma("unroll")                                                        \
        for (int nt = 0; nt < 8; nt++) {                                         \
            sc[nt][0] = exp2f(sc[nt][0] - mn0); rs0 += sc[nt][0];                \
            sc[nt][1] = exp2f(sc[nt][1] - mn0); rs0 += sc[nt][1];                \
            sc[nt][2] = exp2f(sc[nt][2] - mn1); rs1 += sc[nt][2];                \
            sc[nt][3] = exp2f(sc[nt][3] - mn1); rs1 += sc[nt][3];                \
        }                                                                        \
        rs0 += __shfl_xor_sync(0xffffffffu, rs0, 1);                             \
        rs0 += __shfl_xor_sync(0xffffffffu, rs0, 2);                             \
        rs1 += __shfl_xor_sync(0xffffffffu, rs1, 1);                             \
        rs1 += __shfl_xor_sync(0xffffffffu, rs1, 2);                             \
        l0 = l0 * al0 + rs0;                                                     \
        l1 = l1 * al1 + rs1;                                                     \
        _Pragma("unroll")                                                        \
        for (int nt = 0; nt < 16; nt++) {                                        \
            oacc[nt][0] *= al0; oacc[nt][1] *= al0;                              \
            oacc[nt][2] *= al1; oacc[nt][3] *= al1;                              \
        }                                                                        \
        uint32_t ph[4][4];                                                       \
        _Pragma("unroll")                                                        \
        for (int ks = 0; ks < 4; ks++) {                                         \
            ph[ks][0] = pack_h2(sc[2 * ks][0],     sc[2 * ks][1]);               \
            ph[ks][1] = pack_h2(sc[2 * ks][2],     sc[2 * ks][3]);               \
            ph[ks][2] = pack_h2(sc[2 * ks + 1][0], sc[2 * ks + 1][1]);           \
            ph[ks][3] = pack_h2(sc[2 * ks + 1][2], sc[2 * ks + 1][3]);           \
        }                                                                        \
        uint32_t vb_ = smBase + 2 * KVBUF + (uint32_t)((kt) & 1) * KVBUF + vBase;\
        _Pragma("unroll")                                                        \
        for (int ks = 0; ks < 4; ks++) {                                         \
            _Pragma("unroll")                                                    \
            for (int np = 0; np < 8; np++) {                                     \
                uint32_t b0_, b1_, b2_, b3_;                                     \
                ldsm_x4_t(b0_, b1_, b2_, b3_,                                    \
                          vb_ + np * 32 + ks * (16 * AST2 * 2));                 \
                mma_f16(oacc[2 * np],     ph[ks][0], ph[ks][1], ph[ks][2],       \
                        ph[ks][3], b0_, b1_);                                    \
                mma_f16(oacc[2 * np + 1], ph[ks][0], ph[ks][1], ph[ks][2],       \
                        ph[ks][3], b2_, b3_);                                    \
            }                                                                    \
        }                                                                        \
    } while (0)

    asm volatile("cp.async.wait_group 1;");
    __syncthreads();
    QK_TILE(0, sA);

    for (int kt = 0; kt < NKV; kt += 2) {
        ATTN_BODY(kt, sA, sB);
        ATTN_BODY(kt + 1, sB, sA);
    }

    float il0 = 1.f / l0, il1 = 1.f / l1;
    __half* ob = g_oh + ((size_t)b * SEQ + (size_t)qt * 128 + warp * 16) * DIMM + h * HD;
#pragma unroll
    for (int nt = 0; nt < 16; nt++) {
        int c = nt * 8 + q * 2;
        *(uint32_t*)&ob[(size_t)g * DIMM + c] =
            pack_h2(oacc[nt][0] * il0, oacc[nt][1] * il0);
        *(uint32_t*)&ob[(size_t)(g + 8) * DIMM + c] =
            pack_h2(oacc[nt][2] * il1, oacc[nt][3] * il1);
    }
}

// ---------------------------------------------------------------------------
extern "C" void kernel_launch(void* const* d_in, const int* in_sizes, int n_in,
                              void* d_out, int out_size)
{
    const float* x  = (const float*)d_in[0];
    const float* wq = (const float*)d_in[1];
    const float* wk = (const float*)d_in[2];
    const float* wv = (const float*)d_in[3];
    const float* wo = (const float*)d_in[4];
    float* out = (float*)d_out;

    __half *xh, *qkv, *oh, *wt, *wot;
    cudaGetSymbolAddress((void**)&xh,  g_xh);
    cudaGetSymbolAddress((void**)&qkv, g_qkv);
    cudaGetSymbolAddress((void**)&oh,  g_oh);
    cudaGetSymbolAddress((void**)&wt,  g_wt);
    cudaGetSymbolAddress((void**)&wot, g_wot);

    cudaFuncSetAttribute(gemm_f16_kernel<__half>,
                         cudaFuncAttributeMaxDynamicSharedMemorySize, GEMM_SMEM);
    cudaFuncSetAttribute(gemm_f16_kernel<float>,
                         cudaFuncAttributeMaxDynamicSharedMemorySize, GEMM_SMEM);
    cudaFuncSetAttribute(attn_kernel,
                         cudaFuncAttributeMaxDynamicSharedMemorySize, ATTN_SMEM);

    // scale = log2(e) / sqrt(HD): softmax computed in base-2 domain
    const float qscale = 1.44269504088896f * 0.08838834764831845f;

    // --- fused pre-pass (1 launch: 4 weight transposes + x conversion) ---
    prep_kernel<<<dim3(DIMM / 32, DIMM / 32, 5), dim3(32, 8)>>>(
        x, wq, wk, wv, wo, qscale);

    // --- fused QKV projection: [MROWS, 6144] ---
    gemm_f16_kernel<__half><<<dim3(QKVD / 128, MROWS / 128), 256, GEMM_SMEM>>>(
        xh, wt, qkv, MROWS, QKVD, DIMM);

    // --- attention ---
    attn_kernel<<<dim3(SEQ / 128, NHEAD, NBATCH), 256, ATTN_SMEM>>>();

    // --- output projection (fp32 out) ---
    gemm_f16_kernel<float><<<dim3(DIMM / 128, MROWS / 128), 256, GEMM_SMEM>>>(
        oh, wot, out, MROWS, DIMM, DIMM);
}